// round 16
// baseline (speedup 1.0000x reference)
#include <cuda_runtime.h>
#include <cuda_bf16.h>
#include <math.h>
#include <stdint.h>

#define BB 8
#define NN 2048
#define KK 1024
#define NP 64            // points per block

// ---------------- device state ----------------
__device__ float d_mean0[BB*3], d_mean1[BB*3];
__device__ float d_posesJ[7*12];
__device__ float d_gpose[BB*12];
__device__ float d_igtinv[BB*12];
__device__ float d_estg[BB*12];
__device__ float d_f0[BB*KK], d_fj[BB*6*KK], d_f1[BB*KK];
__device__ float d_J[BB*KK*6];
__device__ float d_Hinv[BB*36];
__device__ float d_r[BB*KK];
__device__ float d_lpart[64];
__device__ float d_hpart[BB*8*21];
__device__ float d_upart[BB*8*6];

typedef unsigned long long u64;

// ---------------- helpers ----------------
__device__ __forceinline__ void atomicMaxF(float* addr, float val) {
    if (val >= 0.f) atomicMax((int*)addr, __float_as_int(val));
    else            atomicMin((unsigned int*)addr, __float_as_uint(val));
}
__device__ __forceinline__ u64 dup2(float a) {
    u64 r; asm("mov.b64 %0,{%1,%1};" : "=l"(r) : "f"(a)); return r;
}
__device__ __forceinline__ u64 pk2(float a, float b) {
    u64 r; asm("mov.b64 %0,{%1,%2};" : "=l"(r) : "f"(a), "f"(b)); return r;
}
__device__ __forceinline__ void unpk2(u64 v, float& a, float& b) {
    asm("mov.b64 {%0,%1},%2;" : "=f"(a), "=f"(b) : "l"(v));
}
__device__ __forceinline__ void fma2(u64& d, u64 a, u64 b) {
    asm("fma.rn.f32x2 %0,%1,%2,%0;" : "+l"(d) : "l"(a), "l"(b));
}
__device__ __forceinline__ void cp16(uint32_t dst, const void* src) {
    asm volatile("cp.async.cg.shared.global [%0], [%1], 16;\n" :: "r"(dst), "l"(src));
}
#define CP_COMMIT() asm volatile("cp.async.commit_group;\n" ::: "memory")

// se3_exp (double internals), output 3x4 row-major float
__device__ void se3_exp_d(const double w[3], const double v[3], float out[12]) {
    double t2 = w[0]*w[0] + w[1]*w[1] + w[2]*w[2];
    double t = sqrt(t2);
    double A, Bc, Cc;
    if (t < 1e-6) {
        A  = 1.0 - t2/6.0;  Bc = 0.5 - t2/24.0;  Cc = 1.0/6.0 - t2/120.0;
    } else {
        double st = sin(t), ct = cos(t);
        A = st/t;  Bc = (1.0-ct)/t2;  Cc = (t-st)/(t2*t);
    }
    double W[3][3] = {{0.0,-w[2],w[1]},{w[2],0.0,-w[0]},{-w[1],w[0],0.0}};
    double W2m[3][3];
    for (int i = 0; i < 3; i++)
        for (int j = 0; j < 3; j++)
            W2m[i][j] = w[i]*w[j] - (i==j ? t2 : 0.0);
    double R[3][3], V[3][3];
    for (int i = 0; i < 3; i++)
        for (int j = 0; j < 3; j++) {
            double I = (i==j) ? 1.0 : 0.0;
            R[i][j] = I + A*W[i][j] + Bc*W2m[i][j];
            V[i][j] = I + Bc*W[i][j] + Cc*W2m[i][j];
        }
    for (int i = 0; i < 3; i++) {
        double p = V[i][0]*v[0] + V[i][1]*v[1] + V[i][2]*v[2];
        out[i*4+0] = (float)R[i][0]; out[i*4+1] = (float)R[i][1];
        out[i*4+2] = (float)R[i][2]; out[i*4+3] = (float)p;
    }
}

// ---------------- means (blocks 0..7) + setup (block 8) ----------------
__global__ void prep_kernel(const float* __restrict__ p_tgt, const float* __restrict__ p_src,
                            const float* __restrict__ dt, const float* __restrict__ igt_twist) {
    int tid = threadIdx.x;
    if (blockIdx.x < 8) {
        int b = blockIdx.x;
        float a[6] = {0,0,0,0,0,0};
        for (int n = tid; n < NN; n += 256) {
            const float* pt = p_tgt + ((size_t)b*NN + n)*3;
            const float* ps = p_src + ((size_t)b*NN + n)*3;
            a[0] += pt[0]; a[1] += pt[1]; a[2] += pt[2];
            a[3] += ps[0]; a[4] += ps[1]; a[5] += ps[2];
        }
        for (int off = 16; off; off >>= 1)
            #pragma unroll
            for (int q = 0; q < 6; q++) a[q] += __shfl_down_sync(0xffffffffu, a[q], off);
        __shared__ float sm[8][6];
        int lane = tid & 31, w = tid >> 5;
        if (lane == 0) { for (int q = 0; q < 6; q++) sm[w][q] = a[q]; }
        __syncthreads();
        if (tid < 6) {
            float s = 0.f;
            for (int w2 = 0; w2 < 8; w2++) s += sm[w2][tid];
            s *= (1.0f / NN);
            if (tid < 3) d_mean0[b*3 + tid] = s;
            else         d_mean1[b*3 + tid - 3] = s;
        }
    } else {
        if (tid < 7) {
            float out[12];
            if (tid == 0) {
                float I[12] = {1,0,0,0, 0,1,0,0, 0,0,1,0};
                for (int i = 0; i < 12; i++) out[i] = I[i];
            } else {
                int j = tid - 1;
                double w[3] = {0,0,0}, v[3] = {0,0,0};
                double val = -(double)__ldg(&dt[j]);
                if (j < 3) w[j] = val; else v[j-3] = val;
                se3_exp_d(w, v, out);
            }
            for (int i = 0; i < 12; i++) d_posesJ[tid*12 + i] = out[i];
        }
        if (tid >= 8 && tid < 16) {
            int b = tid - 8;
            float I[12] = {1,0,0,0, 0,1,0,0, 0,0,1,0};
            for (int i = 0; i < 12; i++) d_gpose[b*12 + i] = I[i];
        }
        if (tid >= 16 && tid < 24) {
            int b = tid - 16;
            double w[3], v[3];
            for (int i = 0; i < 3; i++) { w[i] = igt_twist[b*6 + i]; v[i] = igt_twist[b*6 + 3 + i]; }
            float g[12];
            se3_exp_d(w, v, g);
            float inv[12];
            for (int r = 0; r < 3; r++)
                for (int c = 0; c < 3; c++) inv[r*4 + c] = g[c*4 + r];
            for (int r = 0; r < 3; r++)
                inv[r*4 + 3] = -(g[0*4+r]*g[3] + g[1*4+r]*g[7] + g[2*4+r]*g[11]);
            for (int i = 0; i < 12; i++) d_igtinv[b*12 + i] = inv[i];
        }
    }
}

__global__ void init_f_kernel() {
    int i = blockIdx.x*256 + threadIdx.x;
    if (i < BB*KK) d_f0[i] = -INFINITY;
    else if (i < BB*KK + BB*6*KK) d_fj[i - BB*KK] = -INFINITY;
    else if (i < BB*KK + BB*6*KK + BB*KK) d_f1[i - BB*KK - BB*6*KK] = -INFINITY;
}

// ---------------- fused encode ----------------
// 256 threads, 64 points. Phase B: 64 tiles (4 k-passes x 16 c-tiles of 8 c).
// Per-warp 4-deep ring of 8c x 32k raw tiles (256 floats) + warp-private
// DUP buffer (8c x 68-stride, pre-duplicated (w,w) pairs in j-major chunks).
// Inner loop: zero mov dups; all operand loads are LDS.128.
// SMEM floats:
//   ring+dup: warp w at [w*1568, w*1568+1568): ring 4x256, dup 544 (stride 68)
//   H2T at [13120, 21312)
#define WSTR     1568
#define OFF_DUP  1024           /* within warp region */
#define DSTR     68
#define OFF_H2T  13120
#define STRH2    64
#define SMEMF    21312
#define SMEM_BYTES (SMEMF*4)
// A-phase aliases (dead before phase B):
#define OFF_PTS  0
#define OFF_SW1  192
#define OFF_SB1  384
#define OFF_SB2  448
#define OFF_H1   576            /* 64 x 68 -> ends 4928 */
#define OFF_W2   4928           /* 8192 -> ends 13120 (< OFF_H2T) */

// Warp-local stage of tile t (t = kp*16 + ct): rows c = ct*8..+7, cols w*32..+31.
__device__ __forceinline__ void issue_tile_w(uint32_t sbase, int t,
                                             const float* __restrict__ W3g,
                                             int w, int lane) {
    uint32_t buf = sbase + (uint32_t)(w*WSTR + (t & 3)*256) * 4u;
    int kp = t >> 4, ct = t & 15;
    const float* src = W3g + (size_t)(ct*8)*1024 + kp*256 + w*32;
    #pragma unroll
    for (int i = 0; i < 2; i++) {
        int f4 = i*32 + lane;              // 64 float4 = 8 rows x 8
        int row = f4 >> 3, col4 = f4 & 7;
        cp16(buf + (uint32_t)(row*32 + col4*4)*4u, src + (size_t)row*1024 + col4*4);
    }
}

template<int MODE>
__global__ __launch_bounds__(256, 2)
void encode_kernel(const float* __restrict__ P,
                   const float* __restrict__ W1g, const float* __restrict__ b1g,
                   const float* __restrict__ W2g, const float* __restrict__ b2g,
                   const float* __restrict__ W3g, const float* __restrict__ b3g) {
    extern __shared__ float sm[];
    int tid = threadIdx.x;
    uint32_t sbase = (uint32_t)__cvta_generic_to_shared(sm);

    int b; const float* pose; const float* mean; float* out;
    if (MODE == 0) {
        int bm = blockIdx.y;
        b = bm / 7; int m = bm % 7;
        pose = d_posesJ + m*12;
        mean = d_mean0 + b*3;
        out  = (m == 0) ? (d_f0 + b*KK) : (d_fj + ((size_t)b*6 + (m-1))*KK);
    } else {
        b = blockIdx.y;
        pose = d_gpose + b*12;
        mean = d_mean1 + b*3;
        out  = d_f1 + b*KK;
    }

    // phase A0: stage weights + transform points
    {
        const float4* w2v = (const float4*)W2g;
        #pragma unroll
        for (int i = 0; i < 8; i++)
            *(float4*)&sm[OFF_W2 + (tid + i*256)*4] = w2v[tid + i*256];
    }
    if (tid >= 64 && tid < 256) sm[OFF_SW1 + tid - 64] = W1g[tid - 64];
    if (tid < 64)  sm[OFF_SB1 + tid] = b1g[tid];
    if (tid >= 64 && tid < 192) sm[OFF_SB2 + tid - 64] = b2g[tid - 64];
    if (tid < NP) {
        int n = blockIdx.x * NP + tid;
        const float* pp = P + ((size_t)b*NN + n)*3;
        float dx = pp[0] - mean[0], dy = pp[1] - mean[1], dz = pp[2] - mean[2];
        sm[OFF_PTS + tid*3 + 0] = pose[0]*dx + pose[1]*dy + pose[2]*dz  + pose[3];
        sm[OFF_PTS + tid*3 + 1] = pose[4]*dx + pose[5]*dy + pose[6]*dz  + pose[7];
        sm[OFF_PTS + tid*3 + 2] = pose[8]*dx + pose[9]*dy + pose[10]*dz + pose[11];
    }
    __syncthreads();

    // phase A1: h1 = relu(pt @ W1 + b1), 64 x 64 (stride 68)
    #pragma unroll
    for (int i = 0; i < 16; i++) {
        int idx = tid + i*256;
        int p = idx >> 6, c1 = idx & 63;
        float x = sm[OFF_PTS + p*3 + 0], y = sm[OFF_PTS + p*3 + 1], z = sm[OFF_PTS + p*3 + 2];
        float v = sm[OFF_SB1 + c1];
        v = fmaf(x, sm[OFF_SW1 + c1],       v);
        v = fmaf(y, sm[OFF_SW1 + 64 + c1],  v);
        v = fmaf(z, sm[OFF_SW1 + 128 + c1], v);
        sm[OFF_H1 + p*68 + c1] = fmaxf(v, 0.f);
    }
    __syncthreads();

    // phase A2: h2T[c2][p] = relu(h1[p] @ W2[:,c2] + b2), f32x2 accumulation
    {
        int p = tid >> 2, r = tid & 3;
        u64 acc2[16];
        #pragma unroll
        for (int q = 0; q < 8; q++) {
            int c2 = r*4 + q*16;
            acc2[q*2+0] = pk2(sm[OFF_SB2 + c2],     sm[OFF_SB2 + c2 + 1]);
            acc2[q*2+1] = pk2(sm[OFF_SB2 + c2 + 2], sm[OFF_SB2 + c2 + 3]);
        }
        #pragma unroll
        for (int half = 0; half < 2; half++) {
            float hr[32];
            #pragma unroll
            for (int i = 0; i < 8; i++) {
                float4 h4 = *(const float4*)&sm[OFF_H1 + p*68 + half*32 + i*4];
                hr[i*4+0] = h4.x; hr[i*4+1] = h4.y; hr[i*4+2] = h4.z; hr[i*4+3] = h4.w;
            }
            #pragma unroll 8
            for (int c1i = 0; c1i < 32; c1i++) {
                int c1 = half*32 + c1i;
                u64 hd = dup2(hr[c1i]);
                #pragma unroll
                for (int q = 0; q < 8; q++) {
                    int c2 = r*4 + q*16;
                    ulonglong2 w2 = *(const ulonglong2*)&sm[OFF_W2 + c1*128 + c2];
                    fma2(acc2[q*2+0], hd, w2.x);
                    fma2(acc2[q*2+1], hd, w2.y);
                }
            }
        }
        #pragma unroll
        for (int q = 0; q < 8; q++) {
            int c2 = r*4 + q*16;
            float v0, v1, v2, v3;
            unpk2(acc2[q*2+0], v0, v1);
            unpk2(acc2[q*2+1], v2, v3);
            sm[OFF_H2T + (c2+0)*STRH2 + p] = fmaxf(v0, 0.f);
            sm[OFF_H2T + (c2+1)*STRH2 + p] = fmaxf(v1, 0.f);
            sm[OFF_H2T + (c2+2)*STRH2 + p] = fmaxf(v2, 0.f);
            sm[OFF_H2T + (c2+3)*STRH2 + p] = fmaxf(v3, 0.f);
        }
    }
    __syncthreads();   // H2T ready; ring/dup region free. LAST block-wide barrier.

    // phase B: barrier-free, warp-private ring + dup buffer
    int lane = tid & 31, w = tid >> 5;
    int pl = lane & 7, kl = lane >> 3;
    const float* hbase = &sm[OFF_H2T + pl*4];
    float* wreg = &sm[w*WSTR];
    float* dupb = wreg + OFF_DUP;
    int cdup = lane >> 2, kg = lane & 3;
    u64 acc[4][8];

    issue_tile_w(sbase, 0, W3g, w, lane); CP_COMMIT();
    issue_tile_w(sbase, 1, W3g, w, lane); CP_COMMIT();
    issue_tile_w(sbase, 2, W3g, w, lane); CP_COMMIT();

    for (int t = 0; t < 64; t++) {
        int kp = t >> 4, ct = t & 15;
        if (t < 62)      asm volatile("cp.async.wait_group 2;\n" ::: "memory");
        else if (t == 62) asm volatile("cp.async.wait_group 1;\n" ::: "memory");
        else              asm volatile("cp.async.wait_group 0;\n" ::: "memory");
        __syncwarp();

        // dup pass: raw tile -> pre-duplicated j-major layout (stride 68)
        {
            const float* src = wreg + (t & 3)*256 + cdup*32 + kg*8;
            float4 v0 = *(const float4*)src;
            float4 v1 = *(const float4*)(src + 4);
            float* dst = dupb + cdup*DSTR + kg*4;
            *(float4*)(dst +  0) = make_float4(v0.x, v0.x, v0.y, v0.y);
            *(float4*)(dst + 16) = make_float4(v0.z, v0.z, v0.w, v0.w);
            *(float4*)(dst + 32) = make_float4(v1.x, v1.x, v1.y, v1.y);
            *(float4*)(dst + 48) = make_float4(v1.z, v1.z, v1.w, v1.w);
        }
        __syncwarp();

        if (t + 3 < 64) { issue_tile_w(sbase, t + 3, W3g, w, lane); CP_COMMIT(); }

        if (ct == 0) {
            #pragma unroll
            for (int i = 0; i < 4; i++)
                #pragma unroll
                for (int j = 0; j < 8; j++) acc[i][j] = 0ull;
        }

        const float* hrow = hbase + (ct*8)*STRH2;
        const float* wdk = dupb + kl*4;

        #pragma unroll
        for (int c = 0; c < 8; c++) {
            ulonglong2 hA = *(const ulonglong2*)&hrow[c*STRH2];
            ulonglong2 hB = *(const ulonglong2*)&hrow[c*STRH2 + 32];
            ulonglong2 w01 = *(const ulonglong2*)&wdk[c*DSTR];
            ulonglong2 w23 = *(const ulonglong2*)&wdk[c*DSTR + 16];
            ulonglong2 w45 = *(const ulonglong2*)&wdk[c*DSTR + 32];
            ulonglong2 w67 = *(const ulonglong2*)&wdk[c*DSTR + 48];
            fma2(acc[0][0], hA.x, w01.x); fma2(acc[1][0], hA.y, w01.x);
            fma2(acc[2][0], hB.x, w01.x); fma2(acc[3][0], hB.y, w01.x);
            fma2(acc[0][1], hA.x, w01.y); fma2(acc[1][1], hA.y, w01.y);
            fma2(acc[2][1], hB.x, w01.y); fma2(acc[3][1], hB.y, w01.y);
            fma2(acc[0][2], hA.x, w23.x); fma2(acc[1][2], hA.y, w23.x);
            fma2(acc[2][2], hB.x, w23.x); fma2(acc[3][2], hB.y, w23.x);
            fma2(acc[0][3], hA.x, w23.y); fma2(acc[1][3], hA.y, w23.y);
            fma2(acc[2][3], hB.x, w23.y); fma2(acc[3][3], hB.y, w23.y);
            fma2(acc[0][4], hA.x, w45.x); fma2(acc[1][4], hA.y, w45.x);
            fma2(acc[2][4], hB.x, w45.x); fma2(acc[3][4], hB.y, w45.x);
            fma2(acc[0][5], hA.x, w45.y); fma2(acc[1][5], hA.y, w45.y);
            fma2(acc[2][5], hB.x, w45.y); fma2(acc[3][5], hB.y, w45.y);
            fma2(acc[0][6], hA.x, w67.x); fma2(acc[1][6], hA.y, w67.x);
            fma2(acc[2][6], hB.x, w67.x); fma2(acc[3][6], hB.y, w67.x);
            fma2(acc[0][7], hA.x, w67.y); fma2(acc[1][7], hA.y, w67.y);
            fma2(acc[2][7], hB.x, w67.y); fma2(acc[3][7], hB.y, w67.y);
        }
        __syncwarp();   // all lanes done reading dupb before next dup pass

        if (ct == 15) {
            float mx[8];
            #pragma unroll
            for (int j = 0; j < 8; j++) {
                float a0, b0, a1, b1, a2, b2, a3, b3;
                unpk2(acc[0][j], a0, b0); unpk2(acc[1][j], a1, b1);
                unpk2(acc[2][j], a2, b2); unpk2(acc[3][j], a3, b3);
                mx[j] = fmaxf(fmaxf(fmaxf(a0, b0), fmaxf(a1, b1)),
                              fmaxf(fmaxf(a2, b2), fmaxf(a3, b3)));
            }
            #pragma unroll
            for (int off = 1; off < 8; off <<= 1)
                #pragma unroll
                for (int j = 0; j < 8; j++)
                    mx[j] = fmaxf(mx[j], __shfl_xor_sync(0xffffffffu, mx[j], off));
            int k = kp*256 + w*32 + kl*8 + pl;
            atomicMaxF(&out[k], mx[pl] + __ldg(&b3g[k]));
        }
    }
}

// ---------------- J + H partial sums ----------------
__global__ __launch_bounds__(128, 8)
void jh_part_kernel(const float* __restrict__ dt) {
    int blk = blockIdx.x;
    int b = blk >> 3, seg = blk & 7;
    int tid = threadIdx.x;
    int k = seg*128 + tid;
    float dtv[6];
    #pragma unroll
    for (int j = 0; j < 6; j++) dtv[j] = __ldg(&dt[j]);

    float f0k = d_f0[b*KK + k];
    float jv[6];
    #pragma unroll
    for (int j = 0; j < 6; j++) {
        jv[j] = (f0k - d_fj[((size_t)b*6 + j)*KK + k]) / dtv[j];
        d_J[((size_t)b*KK + k)*6 + j] = jv[j];
    }
    float hacc[21];
    int q = 0;
    #pragma unroll
    for (int i = 0; i < 6; i++)
        #pragma unroll
        for (int j = i; j < 6; j++)
            hacc[q++] = jv[i] * jv[j];
    for (int off = 16; off; off >>= 1)
        #pragma unroll
        for (int qq = 0; qq < 21; qq++) hacc[qq] += __shfl_down_sync(0xffffffffu, hacc[qq], off);
    __shared__ float sh[4][21];
    int lane = tid & 31, w = tid >> 5;
    if (lane == 0) { for (int qq = 0; qq < 21; qq++) sh[w][qq] = hacc[qq]; }
    __syncthreads();
    if (tid < 21) {
        float s = sh[0][tid] + sh[1][tid] + sh[2][tid] + sh[3][tid];
        d_hpart[blk*21 + tid] = s;
    }
}

// ---------------- H finalize + Gauss-Jordan ----------------
__global__ void jh_fin_kernel() {
    int b = blockIdx.x, tid = threadIdx.x;
    __shared__ double s[21];
    if (tid < 21) {
        double acc = 0.0;
        for (int seg = 0; seg < 8; seg++) acc += (double)d_hpart[(b*8 + seg)*21 + tid];
        s[tid] = acc;
    }
    __syncthreads();
    if (tid == 0) {
        double H[6][6];
        int q = 0;
        for (int i = 0; i < 6; i++)
            for (int j = i; j < 6; j++) { H[i][j] = s[q]; H[j][i] = s[q]; q++; }
        double M[6][12];
        for (int i = 0; i < 6; i++)
            for (int j = 0; j < 12; j++) M[i][j] = (j < 6) ? H[i][j] : ((j - 6 == i) ? 1.0 : 0.0);
        for (int col = 0; col < 6; col++) {
            int piv = col; double best = fabs(M[col][col]);
            for (int r2 = col + 1; r2 < 6; r2++)
                if (fabs(M[r2][col]) > best) { best = fabs(M[r2][col]); piv = r2; }
            if (piv != col)
                for (int j = 0; j < 12; j++) { double t = M[col][j]; M[col][j] = M[piv][j]; M[piv][j] = t; }
            double inv = 1.0 / M[col][col];
            for (int j = 0; j < 12; j++) M[col][j] *= inv;
            for (int r2 = 0; r2 < 6; r2++) {
                if (r2 == col) continue;
                double f = M[r2][col];
                for (int j = 0; j < 12; j++) M[r2][j] -= f * M[col][j];
            }
        }
        for (int i = 0; i < 6; i++)
            for (int j = 0; j < 6; j++) d_Hinv[b*36 + i*6 + j] = (float)M[i][6 + j];
    }
}

// ---------------- update partial ----------------
__global__ __launch_bounds__(128, 8)
void update_part_kernel() {
    int blk = blockIdx.x;
    int b = blk >> 3, seg = blk & 7;
    int tid = threadIdx.x;
    int k = seg*128 + tid;
    float r = d_f1[b*KK + k] - d_f0[b*KK + k];
    d_r[b*KK + k] = r;
    d_f1[b*KK + k] = -INFINITY;
    float u[6];
    #pragma unroll
    for (int j = 0; j < 6; j++) u[j] = d_J[((size_t)b*KK + k)*6 + j] * r;
    for (int off = 16; off; off >>= 1)
        #pragma unroll
        for (int j = 0; j < 6; j++) u[j] += __shfl_down_sync(0xffffffffu, u[j], off);
    __shared__ float sh[4][6];
    int lane = tid & 31, w = tid >> 5;
    if (lane == 0) { for (int j = 0; j < 6; j++) sh[w][j] = u[j]; }
    __syncthreads();
    if (tid < 6)
        d_upart[blk*6 + tid] = sh[0][tid] + sh[1][tid] + sh[2][tid] + sh[3][tid];
}

// ---------------- update finalize ----------------
__global__ void update_fin_kernel() {
    int b = blockIdx.x, tid = threadIdx.x;
    __shared__ double su[6];
    if (tid < 6) {
        double acc = 0.0;
        for (int seg = 0; seg < 8; seg++) acc += (double)d_upart[(b*8 + seg)*6 + tid];
        su[tid] = acc;
    }
    __syncthreads();
    if (tid == 0) {
        double dx[6];
        for (int i = 0; i < 6; i++) {
            double s2 = 0.0;
            for (int j = 0; j < 6; j++) s2 += (double)d_Hinv[b*36 + i*6 + j] * su[j];
            dx[i] = -s2;
        }
        float E[12];
        double wv[3] = {dx[0], dx[1], dx[2]}, vv[3] = {dx[3], dx[4], dx[5]};
        se3_exp_d(wv, vv, E);
        float G[12];
        for (int i = 0; i < 12; i++) G[i] = d_gpose[b*12 + i];
        float Ng[12];
        for (int r2 = 0; r2 < 3; r2++) {
            for (int c = 0; c < 3; c++)
                Ng[r2*4 + c] = E[r2*4+0]*G[0*4+c] + E[r2*4+1]*G[1*4+c] + E[r2*4+2]*G[2*4+c];
            Ng[r2*4 + 3] = E[r2*4+0]*G[3] + E[r2*4+1]*G[7] + E[r2*4+2]*G[11] + E[r2*4+3];
        }
        for (int i = 0; i < 12; i++) d_gpose[b*12 + i] = Ng[i];
    }
}

// ---------------- est_g ----------------
__global__ void estg_kernel() {
    int tid = threadIdx.x;
    if (tid < 8) {
        int b = tid;
        const float* g = d_gpose + b*12;
        const float* m0 = d_mean0 + b*3;
        const float* m1 = d_mean1 + b*3;
        float e[12];
        for (int r = 0; r < 3; r++) {
            e[r*4+0] = g[r*4+0]; e[r*4+1] = g[r*4+1]; e[r*4+2] = g[r*4+2];
            e[r*4+3] = -(g[r*4+0]*m1[0] + g[r*4+1]*m1[1] + g[r*4+2]*m1[2]) + g[r*4+3] + m0[r];
        }
        for (int i = 0; i < 12; i++) d_estg[b*12 + i] = e[i];
    }
}

// ---------------- loss ----------------
__global__ void loss_kernel(const float* __restrict__ p_src) {
    int bi = blockIdx.x;
    int b = bi >> 3, seg = bi & 7;
    int tid = threadIdx.x;
    int n = seg*256 + tid;
    const float* p = p_src + ((size_t)b*NN + n)*3;
    float x = p[0], y = p[1], z = p[2];
    const float* e = d_estg + b*12;
    const float* q = d_igtinv + b*12;
    float s = 0.f;
    #pragma unroll
    for (int r = 0; r < 3; r++) {
        float ae = e[r*4+0]*x + e[r*4+1]*y + e[r*4+2]*z + e[r*4+3];
        float aq = q[r*4+0]*x + q[r*4+1]*y + q[r*4+2]*z + q[r*4+3];
        s += fabsf(ae - aq);
    }
    __shared__ float sr[256];
    sr[tid] = s;
    __syncthreads();
    for (int st = 128; st; st >>= 1) {
        if (tid < st) sr[tid] += sr[tid + st];
        __syncthreads();
    }
    if (tid == 0) d_lpart[bi] = sr[0];
}

// ---------------- output ----------------
__global__ void finish_kernel(float* __restrict__ out, int out_size) {
    int i = blockIdx.x*256 + threadIdx.x;
    if (i < BB*KK && i < out_size) out[i] = d_r[i];
    if (blockIdx.x == 0 && threadIdx.x == 0 && out_size > BB*KK) {
        double s = 0.0;
        for (int j = 0; j < 64; j++) s += (double)d_lpart[j];
        out[BB*KK] = (float)(s / (double)(BB*NN*3));
    }
}

// ---------------- host ----------------
extern "C" void kernel_launch(void* const* d_in, const int* in_sizes, int n_in,
                              void* d_out, int out_size) {
    const float* p_src = (const float*)d_in[0];
    const float* p_tgt = (const float*)d_in[1];
    const float* igt   = (const float*)d_in[2];
    const float* dt    = (const float*)d_in[3];
    const float* W1    = (const float*)d_in[4];
    const float* b1    = (const float*)d_in[5];
    const float* W2    = (const float*)d_in[6];
    const float* b2    = (const float*)d_in[7];
    const float* W3    = (const float*)d_in[8];
    const float* b3    = (const float*)d_in[9];
    float* out = (float*)d_out;

    cudaFuncSetAttribute(encode_kernel<0>, cudaFuncAttributeMaxDynamicSharedMemorySize, SMEM_BYTES);
    cudaFuncSetAttribute(encode_kernel<1>, cudaFuncAttributeMaxDynamicSharedMemorySize, SMEM_BYTES);

    prep_kernel<<<9, 256>>>(p_tgt, p_src, dt, igt);
    init_f_kernel<<<(BB*KK*2 + BB*6*KK + 255)/256, 256>>>();
    encode_kernel<0><<<dim3(NN/NP, BB*7), 256, SMEM_BYTES>>>(p_tgt, W1, b1, W2, b2, W3, b3);
    jh_part_kernel<<<64, 128>>>(dt);
    jh_fin_kernel<<<8, 32>>>();
    for (int it = 0; it < 5; it++) {
        encode_kernel<1><<<dim3(NN/NP, BB), 256, SMEM_BYTES>>>(p_src, W1, b1, W2, b2, W3, b3);
        update_part_kernel<<<64, 128>>>();
        update_fin_kernel<<<8, 32>>>();
    }
    estg_kernel<<<1, 32>>>();
    loss_kernel<<<64, 256>>>(p_src);
    finish_kernel<<<(BB*KK + 256)/256 + 1, 256>>>(out, out_size);
}

// round 17
// speedup vs baseline: 1.2177x; 1.2177x over previous
#include <cuda_runtime.h>
#include <cuda_bf16.h>
#include <math.h>
#include <stdint.h>

#define BB 8
#define NN 2048
#define KK 1024
#define NP 64            // points per block

// ---------------- device state ----------------
__device__ float d_mean0[BB*3], d_mean1[BB*3];
__device__ float d_posesJ[7*12];
__device__ float d_gpose[BB*12];
__device__ float d_igtinv[BB*12];
__device__ float d_estg[BB*12];
__device__ float d_f0[BB*KK], d_fj[BB*6*KK], d_f1[BB*KK];
__device__ float d_J[BB*KK*6];
__device__ float d_Hinv[BB*36];
__device__ float d_r[BB*KK];
__device__ float d_lpart[64];
__device__ float d_hpart[BB*8*21];
__device__ float d_upart[BB*8*6];

typedef unsigned long long u64;

// ---------------- helpers ----------------
__device__ __forceinline__ void atomicMaxF(float* addr, float val) {
    if (val >= 0.f) atomicMax((int*)addr, __float_as_int(val));
    else            atomicMin((unsigned int*)addr, __float_as_uint(val));
}
__device__ __forceinline__ u64 dup2(float a) {
    u64 r; asm("mov.b64 %0,{%1,%1};" : "=l"(r) : "f"(a)); return r;
}
__device__ __forceinline__ u64 pk2(float a, float b) {
    u64 r; asm("mov.b64 %0,{%1,%2};" : "=l"(r) : "f"(a), "f"(b)); return r;
}
__device__ __forceinline__ void unpk2(u64 v, float& a, float& b) {
    asm("mov.b64 {%0,%1},%2;" : "=f"(a), "=f"(b) : "l"(v));
}
__device__ __forceinline__ void fma2(u64& d, u64 a, u64 b) {
    asm("fma.rn.f32x2 %0,%1,%2,%0;" : "+l"(d) : "l"(a), "l"(b));
}
__device__ __forceinline__ void cp16(uint32_t dst, const void* src) {
    asm volatile("cp.async.cg.shared.global [%0], [%1], 16;\n" :: "r"(dst), "l"(src));
}
#define CP_COMMIT() asm volatile("cp.async.commit_group;\n" ::: "memory")

// se3_exp (double internals), output 3x4 row-major float
__device__ void se3_exp_d(const double w[3], const double v[3], float out[12]) {
    double t2 = w[0]*w[0] + w[1]*w[1] + w[2]*w[2];
    double t = sqrt(t2);
    double A, Bc, Cc;
    if (t < 1e-6) {
        A  = 1.0 - t2/6.0;  Bc = 0.5 - t2/24.0;  Cc = 1.0/6.0 - t2/120.0;
    } else {
        double st = sin(t), ct = cos(t);
        A = st/t;  Bc = (1.0-ct)/t2;  Cc = (t-st)/(t2*t);
    }
    double W[3][3] = {{0.0,-w[2],w[1]},{w[2],0.0,-w[0]},{-w[1],w[0],0.0}};
    double W2m[3][3];
    for (int i = 0; i < 3; i++)
        for (int j = 0; j < 3; j++)
            W2m[i][j] = w[i]*w[j] - (i==j ? t2 : 0.0);
    double R[3][3], V[3][3];
    for (int i = 0; i < 3; i++)
        for (int j = 0; j < 3; j++) {
            double I = (i==j) ? 1.0 : 0.0;
            R[i][j] = I + A*W[i][j] + Bc*W2m[i][j];
            V[i][j] = I + Bc*W[i][j] + Cc*W2m[i][j];
        }
    for (int i = 0; i < 3; i++) {
        double p = V[i][0]*v[0] + V[i][1]*v[1] + V[i][2]*v[2];
        out[i*4+0] = (float)R[i][0]; out[i*4+1] = (float)R[i][1];
        out[i*4+2] = (float)R[i][2]; out[i*4+3] = (float)p;
    }
}

// ---------------- means (blocks 0..7) + setup (block 8) ----------------
__global__ void prep_kernel(const float* __restrict__ p_tgt, const float* __restrict__ p_src,
                            const float* __restrict__ dt, const float* __restrict__ igt_twist) {
    int tid = threadIdx.x;
    if (blockIdx.x < 8) {
        int b = blockIdx.x;
        float a[6] = {0,0,0,0,0,0};
        for (int n = tid; n < NN; n += 256) {
            const float* pt = p_tgt + ((size_t)b*NN + n)*3;
            const float* ps = p_src + ((size_t)b*NN + n)*3;
            a[0] += pt[0]; a[1] += pt[1]; a[2] += pt[2];
            a[3] += ps[0]; a[4] += ps[1]; a[5] += ps[2];
        }
        for (int off = 16; off; off >>= 1)
            #pragma unroll
            for (int q = 0; q < 6; q++) a[q] += __shfl_down_sync(0xffffffffu, a[q], off);
        __shared__ float sm[8][6];
        int lane = tid & 31, w = tid >> 5;
        if (lane == 0) { for (int q = 0; q < 6; q++) sm[w][q] = a[q]; }
        __syncthreads();
        if (tid < 6) {
            float s = 0.f;
            for (int w2 = 0; w2 < 8; w2++) s += sm[w2][tid];
            s *= (1.0f / NN);
            if (tid < 3) d_mean0[b*3 + tid] = s;
            else         d_mean1[b*3 + tid - 3] = s;
        }
    } else {
        if (tid < 7) {
            float out[12];
            if (tid == 0) {
                float I[12] = {1,0,0,0, 0,1,0,0, 0,0,1,0};
                for (int i = 0; i < 12; i++) out[i] = I[i];
            } else {
                int j = tid - 1;
                double w[3] = {0,0,0}, v[3] = {0,0,0};
                double val = -(double)__ldg(&dt[j]);
                if (j < 3) w[j] = val; else v[j-3] = val;
                se3_exp_d(w, v, out);
            }
            for (int i = 0; i < 12; i++) d_posesJ[tid*12 + i] = out[i];
        }
        if (tid >= 8 && tid < 16) {
            int b = tid - 8;
            float I[12] = {1,0,0,0, 0,1,0,0, 0,0,1,0};
            for (int i = 0; i < 12; i++) d_gpose[b*12 + i] = I[i];
        }
        if (tid >= 16 && tid < 24) {
            int b = tid - 16;
            double w[3], v[3];
            for (int i = 0; i < 3; i++) { w[i] = igt_twist[b*6 + i]; v[i] = igt_twist[b*6 + 3 + i]; }
            float g[12];
            se3_exp_d(w, v, g);
            float inv[12];
            for (int r = 0; r < 3; r++)
                for (int c = 0; c < 3; c++) inv[r*4 + c] = g[c*4 + r];
            for (int r = 0; r < 3; r++)
                inv[r*4 + 3] = -(g[0*4+r]*g[3] + g[1*4+r]*g[7] + g[2*4+r]*g[11]);
            for (int i = 0; i < 12; i++) d_igtinv[b*12 + i] = inv[i];
        }
    }
}

__global__ void init_f_kernel() {
    int i = blockIdx.x*256 + threadIdx.x;
    if (i < BB*KK) d_f0[i] = -INFINITY;
    else if (i < BB*KK + BB*6*KK) d_fj[i - BB*KK] = -INFINITY;
    else if (i < BB*KK + BB*6*KK + BB*KK) d_f1[i - BB*KK - BB*6*KK] = -INFINITY;
}

// ---------------- fused encode (R15 winner) ----------------
// 256 threads, 64 points. Phase B: 32 tiles (4 k-passes x 8 c-tiles of 16 c).
// Per-warp 4-deep ring of 16c x 32k tiles; warp-local cp.async; zero
// __syncthreads in phase B.
#define OFF_H2T  16384          /* 128 c x 64 = 8192 */
#define STRH2    64
#define SMEMF    24576
#define SMEM_BYTES (SMEMF*4)
// A-phase aliases inside ring region [0,16384):
#define OFF_PTS  0
#define OFF_SW1  192
#define OFF_SB1  384
#define OFF_SB2  448
#define OFF_H1   576            /* 64 x 68 -> ends 4928 < 8192 */
#define OFF_W2   8192

// Warp-local stage of tile t (t = kp*8 + ct): rows c = ct*16..+15, cols w*32..+31.
__device__ __forceinline__ void issue_tile_w(uint32_t sbase, int t,
                                             const float* __restrict__ W3g,
                                             int w, int lane) {
    uint32_t buf = sbase + (uint32_t)(w*2048 + (t & 3)*512) * 4u;
    int kp = t >> 3, ct = t & 7;
    const float* src = W3g + (size_t)(ct*16)*1024 + kp*256 + w*32;
    #pragma unroll
    for (int i = 0; i < 4; i++) {
        int f4 = i*32 + lane;              // 128 float4 = 16 rows x 8
        int row = f4 >> 3, col4 = f4 & 7;
        cp16(buf + (uint32_t)(row*32 + col4*4)*4u, src + (size_t)row*1024 + col4*4);
    }
}

template<int MODE>
__global__ __launch_bounds__(256, 2)
void encode_kernel(const float* __restrict__ P,
                   const float* __restrict__ W1g, const float* __restrict__ b1g,
                   const float* __restrict__ W2g, const float* __restrict__ b2g,
                   const float* __restrict__ W3g, const float* __restrict__ b3g) {
    extern __shared__ float sm[];
    int tid = threadIdx.x;
    uint32_t sbase = (uint32_t)__cvta_generic_to_shared(sm);

    int b; const float* pose; const float* mean; float* out;
    if (MODE == 0) {
        int bm = blockIdx.y;
        b = bm / 7; int m = bm % 7;
        pose = d_posesJ + m*12;
        mean = d_mean0 + b*3;
        out  = (m == 0) ? (d_f0 + b*KK) : (d_fj + ((size_t)b*6 + (m-1))*KK);
    } else {
        b = blockIdx.y;
        pose = d_gpose + b*12;
        mean = d_mean1 + b*3;
        out  = d_f1 + b*KK;
    }

    // phase A0: stage weights + transform points
    {
        const float4* w2v = (const float4*)W2g;
        #pragma unroll
        for (int i = 0; i < 8; i++)
            *(float4*)&sm[OFF_W2 + (tid + i*256)*4] = w2v[tid + i*256];
    }
    if (tid >= 64 && tid < 256) sm[OFF_SW1 + tid - 64] = W1g[tid - 64];
    if (tid < 64)  sm[OFF_SB1 + tid] = b1g[tid];
    if (tid >= 64 && tid < 192) sm[OFF_SB2 + tid - 64] = b2g[tid - 64];
    if (tid < NP) {
        int n = blockIdx.x * NP + tid;
        const float* pp = P + ((size_t)b*NN + n)*3;
        float dx = pp[0] - mean[0], dy = pp[1] - mean[1], dz = pp[2] - mean[2];
        sm[OFF_PTS + tid*3 + 0] = pose[0]*dx + pose[1]*dy + pose[2]*dz  + pose[3];
        sm[OFF_PTS + tid*3 + 1] = pose[4]*dx + pose[5]*dy + pose[6]*dz  + pose[7];
        sm[OFF_PTS + tid*3 + 2] = pose[8]*dx + pose[9]*dy + pose[10]*dz + pose[11];
    }
    __syncthreads();

    // phase A1: h1 = relu(pt @ W1 + b1), 64 x 64 (stride 68)
    #pragma unroll
    for (int i = 0; i < 16; i++) {
        int idx = tid + i*256;
        int p = idx >> 6, c1 = idx & 63;
        float x = sm[OFF_PTS + p*3 + 0], y = sm[OFF_PTS + p*3 + 1], z = sm[OFF_PTS + p*3 + 2];
        float v = sm[OFF_SB1 + c1];
        v = fmaf(x, sm[OFF_SW1 + c1],       v);
        v = fmaf(y, sm[OFF_SW1 + 64 + c1],  v);
        v = fmaf(z, sm[OFF_SW1 + 128 + c1], v);
        sm[OFF_H1 + p*68 + c1] = fmaxf(v, 0.f);
    }
    __syncthreads();

    // phase A2: h2T[c2][p] = relu(h1[p] @ W2[:,c2] + b2), f32x2 accumulation
    {
        int p = tid >> 2, r = tid & 3;
        u64 acc2[16];
        #pragma unroll
        for (int q = 0; q < 8; q++) {
            int c2 = r*4 + q*16;
            acc2[q*2+0] = pk2(sm[OFF_SB2 + c2],     sm[OFF_SB2 + c2 + 1]);
            acc2[q*2+1] = pk2(sm[OFF_SB2 + c2 + 2], sm[OFF_SB2 + c2 + 3]);
        }
        #pragma unroll
        for (int half = 0; half < 2; half++) {
            float hr[32];
            #pragma unroll
            for (int i = 0; i < 8; i++) {
                float4 h4 = *(const float4*)&sm[OFF_H1 + p*68 + half*32 + i*4];
                hr[i*4+0] = h4.x; hr[i*4+1] = h4.y; hr[i*4+2] = h4.z; hr[i*4+3] = h4.w;
            }
            #pragma unroll 8
            for (int c1i = 0; c1i < 32; c1i++) {
                int c1 = half*32 + c1i;
                u64 hd = dup2(hr[c1i]);
                #pragma unroll
                for (int q = 0; q < 8; q++) {
                    int c2 = r*4 + q*16;
                    ulonglong2 w2 = *(const ulonglong2*)&sm[OFF_W2 + c1*128 + c2];
                    fma2(acc2[q*2+0], hd, w2.x);
                    fma2(acc2[q*2+1], hd, w2.y);
                }
            }
        }
        #pragma unroll
        for (int q = 0; q < 8; q++) {
            int c2 = r*4 + q*16;
            float v0, v1, v2, v3;
            unpk2(acc2[q*2+0], v0, v1);
            unpk2(acc2[q*2+1], v2, v3);
            sm[OFF_H2T + (c2+0)*STRH2 + p] = fmaxf(v0, 0.f);
            sm[OFF_H2T + (c2+1)*STRH2 + p] = fmaxf(v1, 0.f);
            sm[OFF_H2T + (c2+2)*STRH2 + p] = fmaxf(v2, 0.f);
            sm[OFF_H2T + (c2+3)*STRH2 + p] = fmaxf(v3, 0.f);
        }
    }
    __syncthreads();   // H2T ready; ring region free. LAST block-wide barrier.

    // phase B: barrier-free, warp-private W3 ring
    int lane = tid & 31, w = tid >> 5;
    int pl = lane & 7, kl = lane >> 3;
    const float* hbase = &sm[OFF_H2T + pl*4];
    const float* ring = &sm[w*2048];
    u64 acc[4][8];

    issue_tile_w(sbase, 0, W3g, w, lane); CP_COMMIT();
    issue_tile_w(sbase, 1, W3g, w, lane); CP_COMMIT();
    issue_tile_w(sbase, 2, W3g, w, lane); CP_COMMIT();

    for (int t = 0; t < 32; t++) {
        int kp = t >> 3, ct = t & 7;
        if (t < 30)       asm volatile("cp.async.wait_group 2;\n" ::: "memory");
        else if (t == 30) asm volatile("cp.async.wait_group 1;\n" ::: "memory");
        else              asm volatile("cp.async.wait_group 0;\n" ::: "memory");
        __syncwarp();     // tile t visible to all lanes of this warp

        if (t + 3 < 32) { issue_tile_w(sbase, t + 3, W3g, w, lane); CP_COMMIT(); }

        if (ct == 0) {
            #pragma unroll
            for (int i = 0; i < 4; i++)
                #pragma unroll
                for (int j = 0; j < 8; j++) acc[i][j] = 0ull;
        }

        const float* wbase = ring + (t & 3)*512 + kl*8;
        const float* hrow = hbase + (ct*16)*STRH2;

        #pragma unroll 8
        for (int c = 0; c < 16; c++) {
            ulonglong2 hA = *(const ulonglong2*)&hrow[c*STRH2];
            ulonglong2 hB = *(const ulonglong2*)&hrow[c*STRH2 + 32];
            float4 wa = *(const float4*)&wbase[c*32];
            float4 wb = *(const float4*)&wbase[c*32 + 4];
            u64 wd;
            wd = dup2(wa.x);
            fma2(acc[0][0], hA.x, wd); fma2(acc[1][0], hA.y, wd);
            fma2(acc[2][0], hB.x, wd); fma2(acc[3][0], hB.y, wd);
            wd = dup2(wa.y);
            fma2(acc[0][1], hA.x, wd); fma2(acc[1][1], hA.y, wd);
            fma2(acc[2][1], hB.x, wd); fma2(acc[3][1], hB.y, wd);
            wd = dup2(wa.z);
            fma2(acc[0][2], hA.x, wd); fma2(acc[1][2], hA.y, wd);
            fma2(acc[2][2], hB.x, wd); fma2(acc[3][2], hB.y, wd);
            wd = dup2(wa.w);
            fma2(acc[0][3], hA.x, wd); fma2(acc[1][3], hA.y, wd);
            fma2(acc[2][3], hB.x, wd); fma2(acc[3][3], hB.y, wd);
            wd = dup2(wb.x);
            fma2(acc[0][4], hA.x, wd); fma2(acc[1][4], hA.y, wd);
            fma2(acc[2][4], hB.x, wd); fma2(acc[3][4], hB.y, wd);
            wd = dup2(wb.y);
            fma2(acc[0][5], hA.x, wd); fma2(acc[1][5], hA.y, wd);
            fma2(acc[2][5], hB.x, wd); fma2(acc[3][5], hB.y, wd);
            wd = dup2(wb.z);
            fma2(acc[0][6], hA.x, wd); fma2(acc[1][6], hA.y, wd);
            fma2(acc[2][6], hB.x, wd); fma2(acc[3][6], hB.y, wd);
            wd = dup2(wb.w);
            fma2(acc[0][7], hA.x, wd); fma2(acc[1][7], hA.y, wd);
            fma2(acc[2][7], hB.x, wd); fma2(acc[3][7], hB.y, wd);
        }

        if (ct == 7) {
            float mx[8];
            #pragma unroll
            for (int j = 0; j < 8; j++) {
                float a0, b0, a1, b1, a2, b2, a3, b3;
                unpk2(acc[0][j], a0, b0); unpk2(acc[1][j], a1, b1);
                unpk2(acc[2][j], a2, b2); unpk2(acc[3][j], a3, b3);
                mx[j] = fmaxf(fmaxf(fmaxf(a0, b0), fmaxf(a1, b1)),
                              fmaxf(fmaxf(a2, b2), fmaxf(a3, b3)));
            }
            #pragma unroll
            for (int off = 1; off < 8; off <<= 1)
                #pragma unroll
                for (int j = 0; j < 8; j++)
                    mx[j] = fmaxf(mx[j], __shfl_xor_sync(0xffffffffu, mx[j], off));
            int k = kp*256 + w*32 + kl*8 + pl;
            atomicMaxF(&out[k], mx[pl] + __ldg(&b3g[k]));
        }
    }
}

// ---------------- J + H partial sums ----------------
__global__ __launch_bounds__(128, 8)
void jh_part_kernel(const float* __restrict__ dt) {
    int blk = blockIdx.x;
    int b = blk >> 3, seg = blk & 7;
    int tid = threadIdx.x;
    int k = seg*128 + tid;
    float dtv[6];
    #pragma unroll
    for (int j = 0; j < 6; j++) dtv[j] = __ldg(&dt[j]);

    float f0k = d_f0[b*KK + k];
    float jv[6];
    #pragma unroll
    for (int j = 0; j < 6; j++) {
        jv[j] = (f0k - d_fj[((size_t)b*6 + j)*KK + k]) / dtv[j];
        d_J[((size_t)b*KK + k)*6 + j] = jv[j];
    }
    float hacc[21];
    int q = 0;
    #pragma unroll
    for (int i = 0; i < 6; i++)
        #pragma unroll
        for (int j = i; j < 6; j++)
            hacc[q++] = jv[i] * jv[j];
    for (int off = 16; off; off >>= 1)
        #pragma unroll
        for (int qq = 0; qq < 21; qq++) hacc[qq] += __shfl_down_sync(0xffffffffu, hacc[qq], off);
    __shared__ float sh[4][21];
    int lane = tid & 31, w = tid >> 5;
    if (lane == 0) { for (int qq = 0; qq < 21; qq++) sh[w][qq] = hacc[qq]; }
    __syncthreads();
    if (tid < 21) {
        float s = sh[0][tid] + sh[1][tid] + sh[2][tid] + sh[3][tid];
        d_hpart[blk*21 + tid] = s;
    }
}

// ---------------- H finalize + Gauss-Jordan ----------------
__global__ void jh_fin_kernel() {
    int b = blockIdx.x, tid = threadIdx.x;
    __shared__ double s[21];
    if (tid < 21) {
        double acc = 0.0;
        for (int seg = 0; seg < 8; seg++) acc += (double)d_hpart[(b*8 + seg)*21 + tid];
        s[tid] = acc;
    }
    __syncthreads();
    if (tid == 0) {
        double H[6][6];
        int q = 0;
        for (int i = 0; i < 6; i++)
            for (int j = i; j < 6; j++) { H[i][j] = s[q]; H[j][i] = s[q]; q++; }
        double M[6][12];
        for (int i = 0; i < 6; i++)
            for (int j = 0; j < 12; j++) M[i][j] = (j < 6) ? H[i][j] : ((j - 6 == i) ? 1.0 : 0.0);
        for (int col = 0; col < 6; col++) {
            int piv = col; double best = fabs(M[col][col]);
            for (int r2 = col + 1; r2 < 6; r2++)
                if (fabs(M[r2][col]) > best) { best = fabs(M[r2][col]); piv = r2; }
            if (piv != col)
                for (int j = 0; j < 12; j++) { double t = M[col][j]; M[col][j] = M[piv][j]; M[piv][j] = t; }
            double inv = 1.0 / M[col][col];
            for (int j = 0; j < 12; j++) M[col][j] *= inv;
            for (int r2 = 0; r2 < 6; r2++) {
                if (r2 == col) continue;
                double f = M[r2][col];
                for (int j = 0; j < 12; j++) M[r2][j] -= f * M[col][j];
            }
        }
        for (int i = 0; i < 6; i++)
            for (int j = 0; j < 6; j++) d_Hinv[b*36 + i*6 + j] = (float)M[i][6 + j];
    }
}

// ---------------- update partial ----------------
__global__ __launch_bounds__(128, 8)
void update_part_kernel() {
    int blk = blockIdx.x;
    int b = blk >> 3, seg = blk & 7;
    int tid = threadIdx.x;
    int k = seg*128 + tid;
    float r = d_f1[b*KK + k] - d_f0[b*KK + k];
    d_r[b*KK + k] = r;
    d_f1[b*KK + k] = -INFINITY;
    float u[6];
    #pragma unroll
    for (int j = 0; j < 6; j++) u[j] = d_J[((size_t)b*KK + k)*6 + j] * r;
    for (int off = 16; off; off >>= 1)
        #pragma unroll
        for (int j = 0; j < 6; j++) u[j] += __shfl_down_sync(0xffffffffu, u[j], off);
    __shared__ float sh[4][6];
    int lane = tid & 31, w = tid >> 5;
    if (lane == 0) { for (int j = 0; j < 6; j++) sh[w][j] = u[j]; }
    __syncthreads();
    if (tid < 6)
        d_upart[blk*6 + tid] = sh[0][tid] + sh[1][tid] + sh[2][tid] + sh[3][tid];
}

// ---------------- update finalize ----------------
__global__ void update_fin_kernel() {
    int b = blockIdx.x, tid = threadIdx.x;
    __shared__ double su[6];
    if (tid < 6) {
        double acc = 0.0;
        for (int seg = 0; seg < 8; seg++) acc += (double)d_upart[(b*8 + seg)*6 + tid];
        su[tid] = acc;
    }
    __syncthreads();
    if (tid == 0) {
        double dx[6];
        for (int i = 0; i < 6; i++) {
            double s2 = 0.0;
            for (int j = 0; j < 6; j++) s2 += (double)d_Hinv[b*36 + i*6 + j] * su[j];
            dx[i] = -s2;
        }
        float E[12];
        double wv[3] = {dx[0], dx[1], dx[2]}, vv[3] = {dx[3], dx[4], dx[5]};
        se3_exp_d(wv, vv, E);
        float G[12];
        for (int i = 0; i < 12; i++) G[i] = d_gpose[b*12 + i];
        float Ng[12];
        for (int r2 = 0; r2 < 3; r2++) {
            for (int c = 0; c < 3; c++)
                Ng[r2*4 + c] = E[r2*4+0]*G[0*4+c] + E[r2*4+1]*G[1*4+c] + E[r2*4+2]*G[2*4+c];
            Ng[r2*4 + 3] = E[r2*4+0]*G[3] + E[r2*4+1]*G[7] + E[r2*4+2]*G[11] + E[r2*4+3];
        }
        for (int i = 0; i < 12; i++) d_gpose[b*12 + i] = Ng[i];
    }
}

// ---------------- est_g ----------------
__global__ void estg_kernel() {
    int tid = threadIdx.x;
    if (tid < 8) {
        int b = tid;
        const float* g = d_gpose + b*12;
        const float* m0 = d_mean0 + b*3;
        const float* m1 = d_mean1 + b*3;
        float e[12];
        for (int r = 0; r < 3; r++) {
            e[r*4+0] = g[r*4+0]; e[r*4+1] = g[r*4+1]; e[r*4+2] = g[r*4+2];
            e[r*4+3] = -(g[r*4+0]*m1[0] + g[r*4+1]*m1[1] + g[r*4+2]*m1[2]) + g[r*4+3] + m0[r];
        }
        for (int i = 0; i < 12; i++) d_estg[b*12 + i] = e[i];
    }
}

// ---------------- loss ----------------
__global__ void loss_kernel(const float* __restrict__ p_src) {
    int bi = blockIdx.x;
    int b = bi >> 3, seg = bi & 7;
    int tid = threadIdx.x;
    int n = seg*256 + tid;
    const float* p = p_src + ((size_t)b*NN + n)*3;
    float x = p[0], y = p[1], z = p[2];
    const float* e = d_estg + b*12;
    const float* q = d_igtinv + b*12;
    float s = 0.f;
    #pragma unroll
    for (int r = 0; r < 3; r++) {
        float ae = e[r*4+0]*x + e[r*4+1]*y + e[r*4+2]*z + e[r*4+3];
        float aq = q[r*4+0]*x + q[r*4+1]*y + q[r*4+2]*z + q[r*4+3];
        s += fabsf(ae - aq);
    }
    __shared__ float sr[256];
    sr[tid] = s;
    __syncthreads();
    for (int st = 128; st; st >>= 1) {
        if (tid < st) sr[tid] += sr[tid + st];
        __syncthreads();
    }
    if (tid == 0) d_lpart[bi] = sr[0];
}

// ---------------- output ----------------
__global__ void finish_kernel(float* __restrict__ out, int out_size) {
    int i = blockIdx.x*256 + threadIdx.x;
    if (i < BB*KK && i < out_size) out[i] = d_r[i];
    if (blockIdx.x == 0 && threadIdx.x == 0 && out_size > BB*KK) {
        double s = 0.0;
        for (int j = 0; j < 64; j++) s += (double)d_lpart[j];
        out[BB*KK] = (float)(s / (double)(BB*NN*3));
    }
}

// ---------------- host ----------------
extern "C" void kernel_launch(void* const* d_in, const int* in_sizes, int n_in,
                              void* d_out, int out_size) {
    const float* p_src = (const float*)d_in[0];
    const float* p_tgt = (const float*)d_in[1];
    const float* igt   = (const float*)d_in[2];
    const float* dt    = (const float*)d_in[3];
    const float* W1    = (const float*)d_in[4];
    const float* b1    = (const float*)d_in[5];
    const float* W2    = (const float*)d_in[6];
    const float* b2    = (const float*)d_in[7];
    const float* W3    = (const float*)d_in[8];
    const float* b3    = (const float*)d_in[9];
    float* out = (float*)d_out;

    cudaFuncSetAttribute(encode_kernel<0>, cudaFuncAttributeMaxDynamicSharedMemorySize, SMEM_BYTES);
    cudaFuncSetAttribute(encode_kernel<1>, cudaFuncAttributeMaxDynamicSharedMemorySize, SMEM_BYTES);

    prep_kernel<<<9, 256>>>(p_tgt, p_src, dt, igt);
    init_f_kernel<<<(BB*KK*2 + BB*6*KK + 255)/256, 256>>>();
    encode_kernel<0><<<dim3(NN/NP, BB*7), 256, SMEM_BYTES>>>(p_tgt, W1, b1, W2, b2, W3, b3);
    jh_part_kernel<<<64, 128>>>(dt);
    jh_fin_kernel<<<8, 32>>>();
    for (int it = 0; it < 5; it++) {
        encode_kernel<1><<<dim3(NN/NP, BB), 256, SMEM_BYTES>>>(p_src, W1, b1, W2, b2, W3, b3);
        update_part_kernel<<<64, 128>>>();
        update_fin_kernel<<<8, 32>>>();
    }
    estg_kernel<<<1, 32>>>();
    loss_kernel<<<64, 256>>>(p_src);
    finish_kernel<<<(BB*KK + 256)/256 + 1, 256>>>(out, out_size);
}